// round 13
// baseline (speedup 1.0000x reference)
#include <cuda_runtime.h>
#include <cuda_fp16.h>
#include <cstdint>

#define B_  16
#define C_  512
#define HW_ 4096
#define HB_ 8            // half batch

// ---------------- scratch (__device__ globals: allocation-free) ----------------
__device__ float g_xsum[B_ * C_];
__device__ float g_qv[B_ * C_];
__device__ float g_sk[B_ * C_];
__device__ float g_beff[B_ * C_];
__device__ __half g_ahi[(size_t)B_ * C_ * C_];   // attn fp16 [b][c][d]
__device__ __half g_wvhi[C_ * C_];               // wv^T fp16 [c][o]
__device__ __half g_whi[(size_t)B_ * C_ * C_];   // W_eff fp16 [b][m][k]
__device__ __half g_xt[(size_t)B_ * HW_ * C_];   // x^T fp16 [b][n][k]

// ---------------- helpers ----------------
__device__ __forceinline__ uint32_t smem_u32(const void* p) {
    uint32_t a;
    asm("{ .reg .u64 t; cvta.to.shared.u64 t, %1; cvt.u32.u64 %0, t; }" : "=r"(a) : "l"(p));
    return a;
}
__device__ __forceinline__ void cp_async16(uint32_t dst, const void* src) {
    asm volatile("cp.async.cg.shared.global [%0], [%1], 16;" :: "r"(dst), "l"(src) : "memory");
}
__device__ __forceinline__ void cp_commit() {
    asm volatile("cp.async.commit_group;" ::: "memory");
}
template <int N>
__device__ __forceinline__ void cp_wait() {
    asm volatile("cp.async.wait_group %0;" :: "n"(N) : "memory");
}
__device__ __forceinline__ uint32_t sw64(uint32_t off) { return off ^ ((off >> 3) & 0x30); }

__device__ __forceinline__ void ldsm_x4(uint32_t* r, uint32_t addr) {
    asm volatile("ldmatrix.sync.aligned.m8n8.x4.shared.b16 {%0,%1,%2,%3}, [%4];"
                 : "=r"(r[0]), "=r"(r[1]), "=r"(r[2]), "=r"(r[3]) : "r"(addr));
}
__device__ __forceinline__ void mma16816(float* c, const uint32_t* a, const uint32_t* b) {
    asm volatile(
        "mma.sync.aligned.m16n8k16.row.col.f32.f16.f16.f32 "
        "{%0,%1,%2,%3}, {%4,%5,%6,%7}, {%8,%9}, {%0,%1,%2,%3};"
        : "+f"(c[0]), "+f"(c[1]), "+f"(c[2]), "+f"(c[3])
        : "r"(a[0]), "r"(a[1]), "r"(a[2]), "r"(a[3]), "r"(b[0]), "r"(b[1]));
}

__device__ __forceinline__ float warpSum(float v) {
#pragma unroll
    for (int o = 16; o > 0; o >>= 1) v += __shfl_xor_sync(0xffffffffu, v, o);
    return v;
}
__device__ __forceinline__ float warpMax(float v) {
#pragma unroll
    for (int o = 16; o > 0; o >>= 1) v = fmaxf(v, __shfl_xor_sync(0xffffffffu, v, o));
    return v;
}

// ---------------- kernel A: xsum (batch slice) ----------------
__global__ void k_xsum(const float* __restrict__ x, int b0) {
    int row = b0 * C_ + blockIdx.x;
    const float4* p = (const float4*)(x + (size_t)row * HW_);
    float s = 0.f;
#pragma unroll 4
    for (int i = threadIdx.x; i < HW_ / 4; i += 256) {
        float4 v = p[i];
        s += (v.x + v.y) + (v.z + v.w);
    }
    __shared__ float red[8];
    s = warpSum(s);
    if ((threadIdx.x & 31) == 0) red[threadIdx.x >> 5] = s;
    __syncthreads();
    if (threadIdx.x == 0) {
        float t = 0.f;
#pragma unroll
        for (int i = 0; i < 8; i++) t += red[i];
        g_xsum[row] = t;
    }
}

// ---------------- kernel B: transpose+convert x -> g_xt fp16 ----------------
__global__ void k_cvtx(const float* __restrict__ x) {
    __shared__ float tile[64][65];
    int b = blockIdx.z;
    int n0 = blockIdx.x * 64;
    int k0 = blockIdx.y * 64;
    int t = threadIdx.x;
    int tr = t >> 4, tc = t & 15;

    const float* src = x + ((size_t)b * C_ + k0) * HW_ + n0;
#pragma unroll
    for (int i = 0; i < 4; i++) {
        int r = tr + i * 16;  // local k
        float4 v = *(const float4*)(src + (size_t)r * HW_ + tc * 4);
        tile[r][tc * 4 + 0] = v.x;
        tile[r][tc * 4 + 1] = v.y;
        tile[r][tc * 4 + 2] = v.z;
        tile[r][tc * 4 + 3] = v.w;
    }
    __syncthreads();
#pragma unroll
    for (int i = 0; i < 4; i++) {
        int n = tr + i * 16;  // local n
        size_t base = ((size_t)(b * HW_ + n0 + n)) * C_ + k0 + tc * 4;
        float v0 = tile[tc * 4 + 0][n];
        float v1 = tile[tc * 4 + 1][n];
        float v2 = tile[tc * 4 + 2][n];
        float v3 = tile[tc * 4 + 3][n];
        *(__half2*)&g_xt[base]     = __floats2half2_rn(v0, v1);
        *(__half2*)&g_xt[base + 2] = __floats2half2_rn(v2, v3);
    }
}

// ---------------- kernel C: wv^T -> fp16 [c][o] ----------------
__global__ void k_wvt(const float* __restrict__ wv) {
    __shared__ float tile[64][65];
    int o0 = blockIdx.y * 64;
    int c0 = blockIdx.x * 64;
    int t = threadIdx.x;
    int tr = t >> 4, tc = t & 15;

    const float* src = wv + (size_t)(o0)*C_ + c0;
#pragma unroll
    for (int i = 0; i < 4; i++) {
        int r = tr + i * 16;
        float4 v = *(const float4*)(src + (size_t)r * C_ + tc * 4);
        tile[r][tc * 4 + 0] = v.x;
        tile[r][tc * 4 + 1] = v.y;
        tile[r][tc * 4 + 2] = v.z;
        tile[r][tc * 4 + 3] = v.w;
    }
    __syncthreads();
#pragma unroll
    for (int i = 0; i < 4; i++) {
        int c = tr + i * 16;
        size_t base = (size_t)(c0 + c) * C_ + o0 + tc * 4;
        *(__half2*)&g_wvhi[base] = __floats2half2_rn(tile[tc * 4 + 0][c], tile[tc * 4 + 1][c]);
        *(__half2*)&g_wvhi[base + 2] = __floats2half2_rn(tile[tc * 4 + 2][c], tile[tc * 4 + 3][c]);
    }
}

// ---------------- kernel D: qv/sk — 1 warp per output (batch slice) ----------------
__global__ void k_qvsk(const float* __restrict__ wq, const float* __restrict__ bq,
                       const float* __restrict__ wk, const float* __restrict__ bk,
                       const float* __restrict__ y, int b0) {
    int b = b0 + blockIdx.y;
    __shared__ float ys[C_], xs[C_];
    for (int i = threadIdx.x; i < C_; i += 256) {
        ys[i] = y[b * C_ + i];
        xs[i] = g_xsum[b * C_ + i];
    }
    __syncthreads();

    int w = threadIdx.x >> 5, lane = threadIdx.x & 31;
    int o = blockIdx.x * 8 + w;
    const float4* wq4 = (const float4*)(wq + (size_t)o * C_);
    const float4* wk4 = (const float4*)(wk + (size_t)o * C_);
    float aq = 0.f, ak = 0.f;
#pragma unroll
    for (int i = 0; i < 4; i++) {
        int c = lane + 32 * i;
        float4 a = wq4[c], k4 = wk4[c];
        const float* yp = &ys[4 * c];
        const float* xp = &xs[4 * c];
        aq += a.x * yp[0] + a.y * yp[1] + a.z * yp[2] + a.w * yp[3];
        ak += k4.x * xp[0] + k4.y * xp[1] + k4.z * xp[2] + k4.w * xp[3];
    }
    aq = warpSum(aq);
    ak = warpSum(ak);
    if (lane == 0) {
        g_qv[b * C_ + o] = aq + bq[o];
        g_sk[b * C_ + o] = ak + (float)HW_ * bk[o];
    }
}

// ---------------- kernel E: softmax -> attn fp16 + beff (batch slice) ----------------
__global__ void k_softmax(const float* __restrict__ bv, int b0) {
    int b = b0 + blockIdx.y;
    int w = threadIdx.x >> 5, lane = threadIdx.x & 31;
    int c = blockIdx.x * 8 + w;
    __shared__ float sks[C_], bvs[C_];
    for (int i = threadIdx.x; i < C_; i += 256) {
        sks[i] = g_sk[b * C_ + i];
        bvs[i] = bv[i];
    }
    __syncthreads();

    float q = g_qv[b * C_ + c];
    float e[16];
    float m = -3.4e38f;
#pragma unroll
    for (int i = 0; i < 16; i++) {
        e[i] = q * sks[lane + 32 * i];
        m = fmaxf(m, e[i]);
    }
    m = warpMax(m);
    float s = 0.f;
#pragma unroll
    for (int i = 0; i < 16; i++) {
        e[i] = __expf(e[i] - m);
        s += e[i];
    }
    s = warpSum(s);
    float inv = 1.f / s;
    float bacc = 0.f;
    size_t base = ((size_t)(b * C_ + c)) * C_;
#pragma unroll
    for (int i = 0; i < 16; i++) {
        float a = e[i] * inv;
        g_ahi[base + lane + 32 * i] = __float2half(a);
        bacc += a * bvs[lane + 32 * i];
    }
    bacc = warpSum(bacc);
    if (lane == 0) g_beff[b * C_ + c] = bacc;
}

// ---------------- kernel F: W_eff = attn @ wv^T (single fp16 pass, batch slice) ----------------
#define WG_ARR 8192
#define WG_STAGE (2 * WG_ARR)       // 16 KB
#define WG_SMEM (3 * WG_STAGE)      // 48 KB

__global__ __launch_bounds__(256, 2) void k_wgemm(int b0) {
    extern __shared__ char smem[];
    uint32_t sb = smem_u32(smem);
    int t = threadIdx.x;
    int wid = t >> 5, lane = t & 31;
    int wm = wid & 3, wn = wid >> 2;
    int b = b0 + blockIdx.z;
    int tm = blockIdx.y * 128;
    int tn = blockIdx.x * 128;

    const __half* srcAh = g_ahi + ((size_t)b * C_ + tm) * C_;
    const __half* srcBh = g_wvhi + (size_t)tn * C_;

    int lrow = t >> 2;
    int lc = t & 3;

    auto load_stage = [&](int kt, int st) {
        uint32_t base = sb + st * WG_STAGE;
#pragma unroll
        for (int i = 0; i < 2; i++) {
            int row = lrow + i * 64;
            uint32_t soff = sw64((uint32_t)(row * 64 + lc * 16));
            size_t goff = (size_t)row * C_ + kt * 32 + lc * 8;
            cp_async16(base + soff, srcAh + goff);
            cp_async16(base + WG_ARR + soff, srcBh + goff);
        }
        cp_commit();
    };

    float acc[2][8][4];
#pragma unroll
    for (int mt = 0; mt < 2; mt++)
#pragma unroll
        for (int nt = 0; nt < 8; nt++)
#pragma unroll
            for (int q = 0; q < 4; q++) acc[mt][nt][q] = 0.f;

    load_stage(0, 0);
    load_stage(1, 1);

#pragma unroll 1
    for (int kt = 0; kt < 16; kt++) {
        if (kt < 14) cp_wait<1>();
        else cp_wait<0>();
        __syncthreads();
        if (kt + 2 < 16) load_stage(kt + 2, (kt + 2) % 3);

        uint32_t Ah = sb + (kt % 3) * WG_STAGE;
        uint32_t Bh = Ah + WG_ARR;

#pragma unroll
        for (int s = 0; s < 2; s++) {
            uint32_t ah[2][4];
#pragma unroll
            for (int mt = 0; mt < 2; mt++) {
                int row = wm * 32 + mt * 16 + (lane & 15);
                int ch = 2 * s + (lane >> 4);
                uint32_t off = sw64((uint32_t)(row * 64 + ch * 16));
                ldsm_x4(ah[mt], Ah + off);
            }
            uint32_t bh[8][2];
#pragma unroll
            for (int ng = 0; ng < 4; ng++) {
                int row = wn * 64 + ng * 16 + (lane & 7) + ((lane & 16) >> 1);
                int ch = 2 * s + ((lane >> 3) & 1);
                uint32_t off = sw64((uint32_t)(row * 64 + ch * 16));
                uint32_t r4[4];
                ldsm_x4(r4, Bh + off);
                bh[ng * 2 + 0][0] = r4[0]; bh[ng * 2 + 0][1] = r4[1];
                bh[ng * 2 + 1][0] = r4[2]; bh[ng * 2 + 1][1] = r4[3];
            }
#pragma unroll
            for (int mt = 0; mt < 2; mt++)
#pragma unroll
                for (int nt = 0; nt < 8; nt++)
                    mma16816(acc[mt][nt], ah[mt], bh[nt]);
        }
    }

    int r0 = tm + wm * 32 + (lane >> 2);
    int c0 = tn + wn * 64 + (lane & 3) * 2;
#pragma unroll
    for (int mt = 0; mt < 2; mt++) {
#pragma unroll
        for (int half = 0; half < 2; half++) {
            int row = r0 + mt * 16 + half * 8;
            size_t rbase = ((size_t)(b * C_ + row)) * C_;
#pragma unroll
            for (int nt = 0; nt < 8; nt++) {
                int col = c0 + nt * 8;
                *(__half2*)&g_whi[rbase + col] =
                    __floats2half2_rn(acc[mt][nt][half * 2 + 0], acc[mt][nt][half * 2 + 1]);
            }
        }
    }
}

// ---------------- kernel G: main GEMM, single fp16 pass (batch slice) ----------------
#define MM_ARR 8192
#define MM_STAGE (2 * MM_ARR)       // 16 KB (Ah, Bh)
#define MM_SMEM (3 * MM_STAGE)      // 48 KB

__global__ __launch_bounds__(256, 2) void k_main(
    const float* __restrict__ x, float* __restrict__ out,
    const float* __restrict__ gamma, int b0) {
    extern __shared__ char smem[];
    uint32_t sb = smem_u32(smem);
    int t = threadIdx.x;
    int wid = t >> 5, lane = t & 31;
    int wm = wid & 3, wn = wid >> 2;
    int b = b0 + blockIdx.z;
    int tm = blockIdx.y * 128;
    int tn = blockIdx.x * 128;

    const __half* srcAh = g_whi + ((size_t)b * C_ + tm) * C_;
    const __half* srcBh = g_xt + ((size_t)b * HW_ + tn) * C_;

    int lrow = t >> 2;
    int lc = t & 3;

    auto load_stage = [&](int kt, int st) {
        uint32_t base = sb + st * MM_STAGE;
#pragma unroll
        for (int i = 0; i < 2; i++) {
            int row = lrow + i * 64;
            uint32_t soff = sw64((uint32_t)(row * 64 + lc * 16));
            size_t goff = (size_t)row * C_ + kt * 32 + lc * 8;
            cp_async16(base + soff, srcAh + goff);
            cp_async16(base + MM_ARR + soff, srcBh + goff);
        }
        cp_commit();
    };

    float acc[2][8][4];
#pragma unroll
    for (int mt = 0; mt < 2; mt++)
#pragma unroll
        for (int nt = 0; nt < 8; nt++)
#pragma unroll
            for (int q = 0; q < 4; q++) acc[mt][nt][q] = 0.f;

    load_stage(0, 0);
    load_stage(1, 1);

#pragma unroll 1
    for (int kt = 0; kt < 16; kt++) {
        if (kt < 14) cp_wait<1>();
        else cp_wait<0>();
        __syncthreads();
        if (kt + 2 < 16) load_stage(kt + 2, (kt + 2) % 3);

        uint32_t Ah = sb + (kt % 3) * MM_STAGE;
        uint32_t Bh = Ah + MM_ARR;

#pragma unroll
        for (int s = 0; s < 2; s++) {
            uint32_t ah[2][4];
#pragma unroll
            for (int mt = 0; mt < 2; mt++) {
                int row = wm * 32 + mt * 16 + (lane & 15);
                int ch = 2 * s + (lane >> 4);
                uint32_t off = sw64((uint32_t)(row * 64 + ch * 16));
                ldsm_x4(ah[mt], Ah + off);
            }
            uint32_t bh[8][2];
#pragma unroll
            for (int ng = 0; ng < 4; ng++) {
                int row = wn * 64 + ng * 16 + (lane & 7) + ((lane & 16) >> 1);
                int ch = 2 * s + ((lane >> 3) & 1);
                uint32_t off = sw64((uint32_t)(row * 64 + ch * 16));
                uint32_t r4[4];
                ldsm_x4(r4, Bh + off);
                bh[ng * 2 + 0][0] = r4[0]; bh[ng * 2 + 0][1] = r4[1];
                bh[ng * 2 + 1][0] = r4[2]; bh[ng * 2 + 1][1] = r4[3];
            }
#pragma unroll
            for (int mt = 0; mt < 2; mt++)
#pragma unroll
                for (int nt = 0; nt < 8; nt++)
                    mma16816(acc[mt][nt], ah[mt], bh[nt]);
        }
    }

    // epilogue: out = gamma*(acc + beff) + x
    float g = *gamma;
    int r0 = tm + wm * 32 + (lane >> 2);
    int c0 = tn + wn * 64 + (lane & 3) * 2;
#pragma unroll
    for (int mt = 0; mt < 2; mt++) {
#pragma unroll
        for (int half = 0; half < 2; half++) {
            int row = r0 + mt * 16 + half * 8;
            float be = g_beff[b * C_ + row];
            const float2* xr = (const float2*)(x + ((size_t)b * C_ + row) * HW_ + c0);
            float2* orow = (float2*)(out + ((size_t)b * C_ + row) * HW_ + c0);
#pragma unroll
            for (int nt = 0; nt < 8; nt++) {
                float2 xv = xr[nt * 4];
                float2 o;
                o.x = g * (acc[mt][nt][half * 2 + 0] + be) + xv.x;
                o.y = g * (acc[mt][nt][half * 2 + 1] + be) + xv.y;
                orow[nt * 4] = o;
            }
        }
    }
}

// ---------------- launch: minimal 2-slice pipeline (2 streams, 3 events) ----------------
extern "C" void kernel_launch(void* const* d_in, const int* in_sizes, int n_in,
                              void* d_out, int out_size) {
    const float* x = (const float*)d_in[0];
    const float* y = (const float*)d_in[1];
    const float* wq = (const float*)d_in[2];
    const float* bq = (const float*)d_in[3];
    const float* wk = (const float*)d_in[4];
    const float* bk = (const float*)d_in[5];
    const float* wv = (const float*)d_in[6];
    const float* bv = (const float*)d_in[7];
    const float* gamma = (const float*)d_in[8];
    float* out = (float*)d_out;

    static cudaStream_t sA = nullptr;
    static cudaEvent_t evRoot = nullptr, evWg0 = nullptr, evWg1 = nullptr;
    static bool configured = false;
    if (!configured) {
        cudaFuncSetAttribute(k_wgemm, cudaFuncAttributeMaxDynamicSharedMemorySize, WG_SMEM);
        cudaFuncSetAttribute(k_main, cudaFuncAttributeMaxDynamicSharedMemorySize, MM_SMEM);
        cudaStreamCreateWithFlags(&sA, cudaStreamNonBlocking);
        cudaEventCreateWithFlags(&evRoot, cudaEventDisableTiming);
        cudaEventCreateWithFlags(&evWg0, cudaEventDisableTiming);
        cudaEventCreateWithFlags(&evWg1, cudaEventDisableTiming);
        configured = true;
    }

    // fork sA off the capture stream
    cudaEventRecord(evRoot, 0);
    cudaStreamWaitEvent(sA, evRoot, 0);

    // sA: wvt, then the pre-chain in two batch halves
    k_wvt<<<dim3(C_ / 64, C_ / 64), 256, 0, sA>>>(wv);
    // half 0
    k_xsum<<<HB_ * C_, 256, 0, sA>>>(x, 0);
    k_qvsk<<<dim3(C_ / 8, HB_), 256, 0, sA>>>(wq, bq, wk, bk, y, 0);
    k_softmax<<<dim3(C_ / 8, HB_), 256, 0, sA>>>(bv, 0);
    k_wgemm<<<dim3(C_ / 128, C_ / 128, HB_), 256, WG_SMEM, sA>>>(0);
    cudaEventRecord(evWg0, sA);
    // half 1
    k_xsum<<<HB_ * C_, 256, 0, sA>>>(x, HB_);
    k_qvsk<<<dim3(C_ / 8, HB_), 256, 0, sA>>>(wq, bq, wk, bk, y, HB_);
    k_softmax<<<dim3(C_ / 8, HB_), 256, 0, sA>>>(bv, HB_);
    k_wgemm<<<dim3(C_ / 128, C_ / 128, HB_), 256, WG_SMEM, sA>>>(HB_);
    cudaEventRecord(evWg1, sA);

    // stream 0: cvtx (overlaps entire pre-chain), then the two main halves
    k_cvtx<<<dim3(HW_ / 64, C_ / 64, B_), 256>>>(x);
    cudaStreamWaitEvent(0, evWg0, 0);
    k_main<<<dim3(HW_ / 128, C_ / 128, HB_), 256, MM_SMEM>>>(x, out, gamma, 0);
    cudaStreamWaitEvent(0, evWg1, 0);
    k_main<<<dim3(HW_ / 128, C_ / 128, HB_), 256, MM_SMEM>>>(x, out, gamma, HB_);
}

// round 14
// speedup vs baseline: 1.0928x; 1.0928x over previous
#include <cuda_runtime.h>
#include <cuda_fp16.h>
#include <cstdint>

#define B_  16
#define C_  512
#define HW_ 4096

// ---------------- scratch (__device__ globals: allocation-free) ----------------
__device__ float g_xsum[B_ * C_];
__device__ float g_qv[B_ * C_];
__device__ float g_sk[B_ * C_];
__device__ float g_beff[B_ * C_];
__device__ __half g_ahi[(size_t)B_ * C_ * C_];   // attn fp16 [b][c][d]
__device__ __half g_wvhi[C_ * C_];               // wv^T fp16 [c][o]
__device__ __half g_whi[(size_t)B_ * C_ * C_];   // W_eff fp16 [b][m][k]
__device__ __half g_xt[(size_t)B_ * HW_ * C_];   // x^T fp16 [b][n][k]

// ---------------- helpers ----------------
__device__ __forceinline__ uint32_t smem_u32(const void* p) {
    uint32_t a;
    asm("{ .reg .u64 t; cvta.to.shared.u64 t, %1; cvt.u32.u64 %0, t; }" : "=r"(a) : "l"(p));
    return a;
}
__device__ __forceinline__ void cp_async16(uint32_t dst, const void* src) {
    asm volatile("cp.async.cg.shared.global [%0], [%1], 16;" :: "r"(dst), "l"(src) : "memory");
}
__device__ __forceinline__ void cp_commit() {
    asm volatile("cp.async.commit_group;" ::: "memory");
}
template <int N>
__device__ __forceinline__ void cp_wait() {
    asm volatile("cp.async.wait_group %0;" :: "n"(N) : "memory");
}
// 128B-row swizzle: sw128(row*128 + c*16) = row*128 + ((c ^ (row&7))*16)
__device__ __forceinline__ uint32_t sw128(uint32_t off) { return off ^ ((off >> 3) & 0x70); }

__device__ __forceinline__ void ldsm_x4(uint32_t* r, uint32_t addr) {
    asm volatile("ldmatrix.sync.aligned.m8n8.x4.shared.b16 {%0,%1,%2,%3}, [%4];"
                 : "=r"(r[0]), "=r"(r[1]), "=r"(r[2]), "=r"(r[3]) : "r"(addr));
}
__device__ __forceinline__ void mma16816(float* c, const uint32_t* a, const uint32_t* b) {
    asm volatile(
        "mma.sync.aligned.m16n8k16.row.col.f32.f16.f16.f32 "
        "{%0,%1,%2,%3}, {%4,%5,%6,%7}, {%8,%9}, {%0,%1,%2,%3};"
        : "+f"(c[0]), "+f"(c[1]), "+f"(c[2]), "+f"(c[3])
        : "r"(a[0]), "r"(a[1]), "r"(a[2]), "r"(a[3]), "r"(b[0]), "r"(b[1]));
}

__device__ __forceinline__ float warpSum(float v) {
#pragma unroll
    for (int o = 16; o > 0; o >>= 1) v += __shfl_xor_sync(0xffffffffu, v, o);
    return v;
}
__device__ __forceinline__ float warpMax(float v) {
#pragma unroll
    for (int o = 16; o > 0; o >>= 1) v = fmaxf(v, __shfl_xor_sync(0xffffffffu, v, o));
    return v;
}

// ---------------- kernel A: xsum[b,c] = sum_n x[b,c,n] ----------------
__global__ void k_xsum(const float* __restrict__ x) {
    int row = blockIdx.x;
    const float4* p = (const float4*)(x + (size_t)row * HW_);
    float s = 0.f;
#pragma unroll 4
    for (int i = threadIdx.x; i < HW_ / 4; i += 256) {
        float4 v = p[i];
        s += (v.x + v.y) + (v.z + v.w);
    }
    __shared__ float red[8];
    s = warpSum(s);
    if ((threadIdx.x & 31) == 0) red[threadIdx.x >> 5] = s;
    __syncthreads();
    if (threadIdx.x == 0) {
        float t = 0.f;
#pragma unroll
        for (int i = 0; i < 8; i++) t += red[i];
        g_xsum[row] = t;
    }
}

// ---------------- kernel B: transpose+convert x -> g_xt fp16 [b][n][k] ----------------
__global__ void k_cvtx(const float* __restrict__ x) {
    __shared__ float tile[64][65];
    int b = blockIdx.z;
    int n0 = blockIdx.x * 64;
    int k0 = blockIdx.y * 64;
    int t = threadIdx.x;
    int tr = t >> 4, tc = t & 15;

    const float* src = x + ((size_t)b * C_ + k0) * HW_ + n0;
#pragma unroll
    for (int i = 0; i < 4; i++) {
        int r = tr + i * 16;  // local k
        float4 v = *(const float4*)(src + (size_t)r * HW_ + tc * 4);
        tile[r][tc * 4 + 0] = v.x;
        tile[r][tc * 4 + 1] = v.y;
        tile[r][tc * 4 + 2] = v.z;
        tile[r][tc * 4 + 3] = v.w;
    }
    __syncthreads();
#pragma unroll
    for (int i = 0; i < 4; i++) {
        int n = tr + i * 16;  // local n
        size_t base = ((size_t)(b * HW_ + n0 + n)) * C_ + k0 + tc * 4;
        float v0 = tile[tc * 4 + 0][n];
        float v1 = tile[tc * 4 + 1][n];
        float v2 = tile[tc * 4 + 2][n];
        float v3 = tile[tc * 4 + 3][n];
        *(__half2*)&g_xt[base]     = __floats2half2_rn(v0, v1);
        *(__half2*)&g_xt[base + 2] = __floats2half2_rn(v2, v3);
    }
}

// ---------------- kernel C: wv^T -> fp16 [c][o] ----------------
__global__ void k_wvt(const float* __restrict__ wv) {
    __shared__ float tile[64][65];
    int o0 = blockIdx.y * 64;
    int c0 = blockIdx.x * 64;
    int t = threadIdx.x;
    int tr = t >> 4, tc = t & 15;

    const float* src = wv + (size_t)(o0)*C_ + c0;
#pragma unroll
    for (int i = 0; i < 4; i++) {
        int r = tr + i * 16;
        float4 v = *(const float4*)(src + (size_t)r * C_ + tc * 4);
        tile[r][tc * 4 + 0] = v.x;
        tile[r][tc * 4 + 1] = v.y;
        tile[r][tc * 4 + 2] = v.z;
        tile[r][tc * 4 + 3] = v.w;
    }
    __syncthreads();
#pragma unroll
    for (int i = 0; i < 4; i++) {
        int c = tr + i * 16;
        size_t base = (size_t)(c0 + c) * C_ + o0 + tc * 4;
        *(__half2*)&g_wvhi[base] = __floats2half2_rn(tile[tc * 4 + 0][c], tile[tc * 4 + 1][c]);
        *(__half2*)&g_wvhi[base + 2] = __floats2half2_rn(tile[tc * 4 + 2][c], tile[tc * 4 + 3][c]);
    }
}

// ---------------- kernel D: qv/sk — 1 warp per output ----------------
__global__ void k_qvsk(const float* __restrict__ wq, const float* __restrict__ bq,
                       const float* __restrict__ wk, const float* __restrict__ bk,
                       const float* __restrict__ y) {
    int b = blockIdx.y;
    __shared__ float ys[C_], xs[C_];
    for (int i = threadIdx.x; i < C_; i += 256) {
        ys[i] = y[b * C_ + i];
        xs[i] = g_xsum[b * C_ + i];
    }
    __syncthreads();

    int w = threadIdx.x >> 5, lane = threadIdx.x & 31;
    int o = blockIdx.x * 8 + w;
    const float4* wq4 = (const float4*)(wq + (size_t)o * C_);
    const float4* wk4 = (const float4*)(wk + (size_t)o * C_);
    float aq = 0.f, ak = 0.f;
#pragma unroll
    for (int i = 0; i < 4; i++) {
        int c = lane + 32 * i;
        float4 a = wq4[c], k4 = wk4[c];
        const float* yp = &ys[4 * c];
        const float* xp = &xs[4 * c];
        aq += a.x * yp[0] + a.y * yp[1] + a.z * yp[2] + a.w * yp[3];
        ak += k4.x * xp[0] + k4.y * xp[1] + k4.z * xp[2] + k4.w * xp[3];
    }
    aq = warpSum(aq);
    ak = warpSum(ak);
    if (lane == 0) {
        g_qv[b * C_ + o] = aq + bq[o];
        g_sk[b * C_ + o] = ak + (float)HW_ * bk[o];
    }
}

// ---------------- kernel E: softmax -> attn fp16 + beff (1 warp/row) ----------------
__global__ void k_softmax(const float* __restrict__ bv) {
    int b = blockIdx.y;
    int w = threadIdx.x >> 5, lane = threadIdx.x & 31;
    int c = blockIdx.x * 8 + w;
    __shared__ float sks[C_], bvs[C_];
    for (int i = threadIdx.x; i < C_; i += 256) {
        sks[i] = g_sk[b * C_ + i];
        bvs[i] = bv[i];
    }
    __syncthreads();

    float q = g_qv[b * C_ + c];
    float e[16];
    float m = -3.4e38f;
#pragma unroll
    for (int i = 0; i < 16; i++) {
        e[i] = q * sks[lane + 32 * i];
        m = fmaxf(m, e[i]);
    }
    m = warpMax(m);
    float s = 0.f;
#pragma unroll
    for (int i = 0; i < 16; i++) {
        e[i] = __expf(e[i] - m);
        s += e[i];
    }
    s = warpSum(s);
    float inv = 1.f / s;
    float bacc = 0.f;
    size_t base = ((size_t)(b * C_ + c)) * C_;
#pragma unroll
    for (int i = 0; i < 16; i++) {
        float a = e[i] * inv;
        g_ahi[base + lane + 32 * i] = __float2half(a);
        bacc += a * bvs[lane + 32 * i];
    }
    bacc = warpSum(bacc);
    if (lane == 0) g_beff[b * C_ + c] = bacc;
}

// ---------------- shared GEMM body: BK=64, 3-stage, 128B swizzled rows ----------------
// A [m][k] fp16 k-contig, B [n][k] fp16 k-contig; 128x128 tile, K=512, NKT=8.
#define G_ARR 16384                  // one operand tile: 128 rows x 128 B
#define G_STAGE (2 * G_ARR)          // 32 KB
#define G_SMEM (3 * G_STAGE)         // 96 KB
#define G_NKT (C_ / 64)              // 8

// ---------------- kernel F: W_eff = attn @ wv^T ----------------
__global__ __launch_bounds__(256, 2) void k_wgemm() {
    extern __shared__ char smem[];
    uint32_t sb = smem_u32(smem);
    int t = threadIdx.x;
    int wid = t >> 5, lane = t & 31;
    int wm = wid & 3, wn = wid >> 2;
    int b = blockIdx.z;
    int tm = blockIdx.y * 128;
    int tn = blockIdx.x * 128;

    const __half* srcAh = g_ahi + ((size_t)b * C_ + tm) * C_;
    const __half* srcBh = g_wvhi + (size_t)tn * C_;

    auto load_stage = [&](int kt, int st) {
        uint32_t base = sb + st * G_STAGE;
#pragma unroll
        for (int i = 0; i < 4; i++) {
            int id = t + i * 256;
            int row = id >> 3, c = id & 7;
            uint32_t soff = sw128((uint32_t)(row * 128 + c * 16));
            size_t goff = (size_t)row * C_ + kt * 64 + c * 8;
            cp_async16(base + soff, srcAh + goff);
            cp_async16(base + G_ARR + soff, srcBh + goff);
        }
        cp_commit();
    };

    float acc[2][8][4];
#pragma unroll
    for (int mt = 0; mt < 2; mt++)
#pragma unroll
        for (int nt = 0; nt < 8; nt++)
#pragma unroll
            for (int q = 0; q < 4; q++) acc[mt][nt][q] = 0.f;

    load_stage(0, 0);
    load_stage(1, 1);

#pragma unroll 1
    for (int kt = 0; kt < G_NKT; kt++) {
        if (kt < G_NKT - 2) cp_wait<1>();
        else cp_wait<0>();
        __syncthreads();
        if (kt + 2 < G_NKT) load_stage(kt + 2, (kt + 2) % 3);

        uint32_t Ah = sb + (kt % 3) * G_STAGE;
        uint32_t Bh = Ah + G_ARR;

#pragma unroll
        for (int s = 0; s < 4; s++) {
            uint32_t ah[2][4];
#pragma unroll
            for (int mt = 0; mt < 2; mt++) {
                int row = wm * 32 + mt * 16 + (lane & 15);
                int ch = 2 * s + (lane >> 4);
                uint32_t off = sw128((uint32_t)(row * 128 + ch * 16));
                ldsm_x4(ah[mt], Ah + off);
            }
            uint32_t bh[8][2];
#pragma unroll
            for (int ng = 0; ng < 4; ng++) {
                int row = wn * 64 + ng * 16 + (lane & 7) + ((lane & 16) >> 1);
                int ch = 2 * s + ((lane >> 3) & 1);
                uint32_t off = sw128((uint32_t)(row * 128 + ch * 16));
                uint32_t r4[4];
                ldsm_x4(r4, Bh + off);
                bh[ng * 2 + 0][0] = r4[0]; bh[ng * 2 + 0][1] = r4[1];
                bh[ng * 2 + 1][0] = r4[2]; bh[ng * 2 + 1][1] = r4[3];
            }
#pragma unroll
            for (int mt = 0; mt < 2; mt++)
#pragma unroll
                for (int nt = 0; nt < 8; nt++)
                    mma16816(acc[mt][nt], ah[mt], bh[nt]);
        }
    }

    int r0 = tm + wm * 32 + (lane >> 2);
    int c0 = tn + wn * 64 + (lane & 3) * 2;
#pragma unroll
    for (int mt = 0; mt < 2; mt++) {
#pragma unroll
        for (int half = 0; half < 2; half++) {
            int row = r0 + mt * 16 + half * 8;
            size_t rbase = ((size_t)(b * C_ + row)) * C_;
#pragma unroll
            for (int nt = 0; nt < 8; nt++) {
                int col = c0 + nt * 8;
                *(__half2*)&g_whi[rbase + col] =
                    __floats2half2_rn(acc[mt][nt][half * 2 + 0], acc[mt][nt][half * 2 + 1]);
            }
        }
    }
}

// ---------------- kernel G: main GEMM + fused epilogue ----------------
__global__ __launch_bounds__(256, 2) void k_main(
    const float* __restrict__ x, float* __restrict__ out,
    const float* __restrict__ gamma) {
    extern __shared__ char smem[];
    uint32_t sb = smem_u32(smem);
    int t = threadIdx.x;
    int wid = t >> 5, lane = t & 31;
    int wm = wid & 3, wn = wid >> 2;
    int b = blockIdx.z;
    int tm = blockIdx.y * 128;
    int tn = blockIdx.x * 128;

    const __half* srcAh = g_whi + ((size_t)b * C_ + tm) * C_;
    const __half* srcBh = g_xt + ((size_t)b * HW_ + tn) * C_;

    auto load_stage = [&](int kt, int st) {
        uint32_t base = sb + st * G_STAGE;
#pragma unroll
        for (int i = 0; i < 4; i++) {
            int id = t + i * 256;
            int row = id >> 3, c = id & 7;
            uint32_t soff = sw128((uint32_t)(row * 128 + c * 16));
            size_t goff = (size_t)row * C_ + kt * 64 + c * 8;
            cp_async16(base + soff, srcAh + goff);
            cp_async16(base + G_ARR + soff, srcBh + goff);
        }
        cp_commit();
    };

    float acc[2][8][4];
#pragma unroll
    for (int mt = 0; mt < 2; mt++)
#pragma unroll
        for (int nt = 0; nt < 8; nt++)
#pragma unroll
            for (int q = 0; q < 4; q++) acc[mt][nt][q] = 0.f;

    load_stage(0, 0);
    load_stage(1, 1);

#pragma unroll 1
    for (int kt = 0; kt < G_NKT; kt++) {
        if (kt < G_NKT - 2) cp_wait<1>();
        else cp_wait<0>();
        __syncthreads();
        if (kt + 2 < G_NKT) load_stage(kt + 2, (kt + 2) % 3);

        uint32_t Ah = sb + (kt % 3) * G_STAGE;
        uint32_t Bh = Ah + G_ARR;

#pragma unroll
        for (int s = 0; s < 4; s++) {
            uint32_t ah[2][4];
#pragma unroll
            for (int mt = 0; mt < 2; mt++) {
                int row = wm * 32 + mt * 16 + (lane & 15);
                int ch = 2 * s + (lane >> 4);
                uint32_t off = sw128((uint32_t)(row * 128 + ch * 16));
                ldsm_x4(ah[mt], Ah + off);
            }
            uint32_t bh[8][2];
#pragma unroll
            for (int ng = 0; ng < 4; ng++) {
                int row = wn * 64 + ng * 16 + (lane & 7) + ((lane & 16) >> 1);
                int ch = 2 * s + ((lane >> 3) & 1);
                uint32_t off = sw128((uint32_t)(row * 128 + ch * 16));
                uint32_t r4[4];
                ldsm_x4(r4, Bh + off);
                bh[ng * 2 + 0][0] = r4[0]; bh[ng * 2 + 0][1] = r4[1];
                bh[ng * 2 + 1][0] = r4[2]; bh[ng * 2 + 1][1] = r4[3];
            }
#pragma unroll
            for (int mt = 0; mt < 2; mt++)
#pragma unroll
                for (int nt = 0; nt < 8; nt++)
                    mma16816(acc[mt][nt], ah[mt], bh[nt]);
        }
    }

    // epilogue: out = gamma*(acc + beff) + x
    float g = *gamma;
    int r0 = tm + wm * 32 + (lane >> 2);
    int c0 = tn + wn * 64 + (lane & 3) * 2;
#pragma unroll
    for (int mt = 0; mt < 2; mt++) {
#pragma unroll
        for (int half = 0; half < 2; half++) {
            int row = r0 + mt * 16 + half * 8;
            float be = g_beff[b * C_ + row];
            const float2* xr = (const float2*)(x + ((size_t)b * C_ + row) * HW_ + c0);
            float2* orow = (float2*)(out + ((size_t)b * C_ + row) * HW_ + c0);
#pragma unroll
            for (int nt = 0; nt < 8; nt++) {
                float2 xv = xr[nt * 4];
                float2 o;
                o.x = g * (acc[mt][nt][half * 2 + 0] + be) + xv.x;
                o.y = g * (acc[mt][nt][half * 2 + 1] + be) + xv.y;
                orow[nt * 4] = o;
            }
        }
    }
}

// ---------------- launch: round-8 forked graph (proven best DAG) ----------------
extern "C" void kernel_launch(void* const* d_in, const int* in_sizes, int n_in,
                              void* d_out, int out_size) {
    const float* x = (const float*)d_in[0];
    const float* y = (const float*)d_in[1];
    const float* wq = (const float*)d_in[2];
    const float* bq = (const float*)d_in[3];
    const float* wk = (const float*)d_in[4];
    const float* bk = (const float*)d_in[5];
    const float* wv = (const float*)d_in[6];
    const float* bv = (const float*)d_in[7];
    const float* gamma = (const float*)d_in[8];
    float* out = (float*)d_out;

    static cudaStream_t s2 = nullptr, s3 = nullptr;
    static cudaEvent_t evRoot = nullptr, evCvt = nullptr, evWvt = nullptr;
    static bool configured = false;
    if (!configured) {
        cudaFuncSetAttribute(k_wgemm, cudaFuncAttributeMaxDynamicSharedMemorySize, G_SMEM);
        cudaFuncSetAttribute(k_main, cudaFuncAttributeMaxDynamicSharedMemorySize, G_SMEM);
        cudaStreamCreateWithFlags(&s2, cudaStreamNonBlocking);
        cudaStreamCreateWithFlags(&s3, cudaStreamNonBlocking);
        cudaEventCreateWithFlags(&evRoot, cudaEventDisableTiming);
        cudaEventCreateWithFlags(&evCvt, cudaEventDisableTiming);
        cudaEventCreateWithFlags(&evWvt, cudaEventDisableTiming);
        configured = true;
    }

    // fork
    cudaEventRecord(evRoot, 0);
    cudaStreamWaitEvent(s2, evRoot, 0);
    cudaStreamWaitEvent(s3, evRoot, 0);

    // branch s2: x transpose/convert (feeds only k_main)
    k_cvtx<<<dim3(HW_ / 64, C_ / 64, B_), 256, 0, s2>>>(x);
    cudaEventRecord(evCvt, s2);

    // branch s3: wv transpose/convert (feeds k_wgemm)
    k_wvt<<<dim3(C_ / 64, C_ / 64), 256, 0, s3>>>(wv);
    cudaEventRecord(evWvt, s3);

    // main chain on stream 0
    k_xsum<<<B_ * C_, 256>>>(x);
    k_qvsk<<<dim3(C_ / 8, B_), 256>>>(wq, bq, wk, bk, y);
    k_softmax<<<dim3(C_ / 8, B_), 256>>>(bv);
    cudaStreamWaitEvent(0, evWvt, 0);
    k_wgemm<<<dim3(C_ / 128, C_ / 128, B_), 256, G_SMEM>>>();
    cudaStreamWaitEvent(0, evCvt, 0);
    k_main<<<dim3(HW_ / 128, C_ / 128, B_), 256, G_SMEM>>>(x, out, gamma);
}